// round 13
// baseline (speedup 1.0000x reference)
#include <cuda_runtime.h>
#include <cuda_fp16.h>
#include <cstdint>
#include <cstddef>

// ---------------- problem constants ----------------
#define M_DIM 8192
#define K_DIM 7168
#define N_DIM 2112           // 1536 + 512 + 64
#define Q_RANK 1536
#define KV_RANK 512
#define ROPE_DIM 64
#define N_GROUPS 12
#define FP8_MAX 448.0f
#define EPS_RMS 1e-6f

#define OUT_QQ   ((size_t)0)
#define OUT_SC   ((size_t)M_DIM * Q_RANK)
#define OUT_KV   (OUT_SC + (size_t)M_DIM * N_GROUPS)
#define OUT_KPE  (OUT_KV + (size_t)M_DIM * KV_RANK)

// ---------------- GEMM tiling ----------------
#define MT 128
#define NT 128
#define KB 64                        // k elems per slab
#define NSLAB (K_DIM / KB)           // 112
#define N_PAD 2176                   // 17 * 128
// Stage: A fp32 128 rows x 256B = 32KB | Bhi fp16 128 rows x 128B = 16KB
#define A_BYTES (32 * 1024)
#define STAGE_BYTES (48 * 1024)
#define SMEM_TOTAL (2 * STAGE_BYTES)        // 96 KB -> 2 CTAs/SM

// ---------------- device scratch (no cudaMalloc allowed) ----------------
__device__ __align__(1024) __half g_Bhi[(size_t)N_PAD * K_DIM];   // [n][k] transposed
__device__ __align__(16)   float  g_scratch[(size_t)M_DIM * N_DIM];

// ---------------- PTX helpers (baseline PTX only: sm_80-era) ----------------
__device__ __forceinline__ uint32_t smem_u32(const void* p) {
    uint32_t a;
    asm("{ .reg .u64 t; cvta.to.shared.u64 t, %1; cvt.u32.u64 %0, t; }" : "=r"(a) : "l"(p));
    return a;
}

__device__ __forceinline__ void cpa16(uint32_t dst, const void* src) {
    asm volatile("cp.async.cg.shared.global [%0], [%1], 16;" :: "r"(dst), "l"(src));
}
#define CP_COMMIT() asm volatile("cp.async.commit_group;" ::: "memory")
#define CP_WAIT0()  asm volatile("cp.async.wait_group 0;"  ::: "memory")

__device__ __forceinline__ void ldsm4(uint32_t* r, uint32_t addr) {
    asm volatile("ldmatrix.sync.aligned.m8n8.x4.shared.b16 {%0,%1,%2,%3}, [%4];"
                 : "=r"(r[0]), "=r"(r[1]), "=r"(r[2]), "=r"(r[3]) : "r"(addr));
}

__device__ __forceinline__ void mma16816(float* c, const uint32_t* a,
                                         uint32_t b0, uint32_t b1) {
    asm volatile(
        "mma.sync.aligned.m16n8k16.row.col.f32.f16.f16.f32 "
        "{%0,%1,%2,%3}, {%4,%5,%6,%7}, {%8,%9}, {%0,%1,%2,%3};"
        : "+f"(c[0]), "+f"(c[1]), "+f"(c[2]), "+f"(c[3])
        : "r"(a[0]), "r"(a[1]), "r"(a[2]), "r"(a[3]), "r"(b0), "r"(b1));
}

// hi/lo split of a float2 into packed fp16 pairs (hi = rn(f), lo = rn(f - hi))
__device__ __forceinline__ void split2(float2 v, uint32_t& hi, uint32_t& lo) {
    __half2 h = __floats2half2_rn(v.x, v.y);
    float2 hf = __half22float2(h);
    __half2 l = __floats2half2_rn(v.x - hf.x, v.y - hf.y);
    hi = *reinterpret_cast<uint32_t*>(&h);
    lo = *reinterpret_cast<uint32_t*>(&l);
}

// ---------------------------------------------------------------------------
// convB: w_qkv_a [K, N] -> transposed fp16 [N_PAD, K] (pad rows zeroed)
// ---------------------------------------------------------------------------
__global__ __launch_bounds__(256)
void convB_kernel(const float* __restrict__ W)
{
    __shared__ float t[32][33];
    const int kt = blockIdx.y * 32;
    const int nt = blockIdx.x * 32;
    const int tx = threadIdx.x & 31, ty = threadIdx.x >> 5;

#pragma unroll
    for (int j = 0; j < 4; j++) {
        int k = kt + ty + j * 8;
        int n = nt + tx;
        t[ty + j * 8][tx] = (n < N_DIM) ? W[(size_t)k * N_DIM + n] : 0.f;
    }
    __syncthreads();
#pragma unroll
    for (int j = 0; j < 4; j++) {
        int n = nt + ty + j * 8;
        int k = kt + tx;
        g_Bhi[(size_t)n * K_DIM + k] = __float2half(t[tx][ty + j * 8]);
    }
}

// ---------------------------------------------------------------------------
// GEMM via mma.sync (HMMA): 128x128 block, 256 threads (8 warps, 4m x 2n),
// warp tile 32x64, fp16 2-product ((Ahi+Alo)*Bhi), 2-stage cp.async pipeline,
// single __syncthreads per slab, 2 CTAs per SM.
//
// This round: A is staged as RAW FP32 (same 32KB smem footprint as hi+lo
// fp16) and hi/lo fragments are built in-register via swizzled LDS.64 +
// cvt.f16x2 — the convA kernel and its 470MB of DRAM traffic are deleted.
// The extra LDS/ALU work rides the idle pipes under the HMMA ceiling.
//
// Stage layout:
//   A fp32 : rows 0-127, 256B/row, 16B-chunk swizzle c ^ ((row&7)<<1)
//   B fp16 : offset 32768, rows 0-127, 128B/row, chunk swizzle c ^ (row&7)
// ---------------------------------------------------------------------------
__global__ __launch_bounds__(256, 2)
void mma_gemm_kernel(const float* __restrict__ Afp32)
{
    extern __shared__ __align__(1024) char smem[];
    const uint32_t sbase = smem_u32(smem);
    const int tid  = threadIdx.x;
    const int bm   = blockIdx.y * MT;
    const int bn   = blockIdx.x * NT;
    const int lane = tid & 31;
    const int wid  = tid >> 5;           // 0..7
    const int wm   = wid & 3;            // m: 4 warps * 32
    const int wn   = wid >> 2;           // n: 2 warps * 64

    const bool active = (bn + wn * 64) < N_DIM;   // tail-tile guard

    // ---- cooperative load ----
    // A: 2 threads per row (tid>>1 = row 0..127), 8 x 16B chunks each.
    const int arow  = tid >> 1;
    const int ahalf = (tid & 1) * 8;
    const char* pA = (const char*)(Afp32 + (size_t)(bm + arow) * K_DIM);
    const uint32_t aDst = sbase + (uint32_t)arow * 256;
    const uint32_t aswr = (uint32_t)((arow & 7) << 1);

    // B: 8 threads per row band, 4 bands (reuse R12 mapping).
    const int rb    = tid >> 3;          // 0..31
    const int chunk = tid & 7;
    const uint32_t bsw = (uint32_t)((chunk ^ (rb & 7)) << 4);
    const uint32_t bDst = sbase + A_BYTES + (uint32_t)rb * 128 + bsw;
    const char* pBh[4];
    bool loadB[4];
#pragma unroll
    for (int j = 0; j < 4; j++) {
        pBh[j] = (const char*)(g_Bhi + (size_t)(bn + j * 32 + rb) * K_DIM) + chunk * 16;
        loadB[j] = (bn + j * 32) < N_DIM;
    }

    auto load_stage = [&](uint32_t soff, int slab) {
        // A fp32: slab k-offset = slab*64 floats = slab*256 bytes
        const char* srcA = pA + (size_t)slab * 256;
#pragma unroll
        for (int i = 0; i < 8; i++) {
            uint32_t c = (uint32_t)(ahalf + i);
            cpa16(soff + aDst + ((c ^ aswr) << 4), srcA + c * 16);
        }
        // B fp16: slab k-offset = slab*128 bytes
#pragma unroll
        for (int j = 0; j < 4; j++) {
            if (loadB[j])
                cpa16(soff + bDst + (uint32_t)j * 4096, pBh[j] + (size_t)slab * 128);
        }
    };

    // ---- fragment address constants ----
    const int lr = lane & 15;
    const int lh = lane >> 4;
    const int l7 = lr & 7;
    const int fr = lane >> 2;            // fragment row within 8 (0..7)
    const int fc = (lane & 3) * 2;       // fragment col pair base

    // A fp32 fragment smem address for (row, col-within-slab)
    auto a_addr = [&](int row, int col) -> uint32_t {
        uint32_t byte = (uint32_t)col * 4;
        uint32_t c = byte >> 4;
        return sbase /*+stage added later*/ + (uint32_t)row * 256 +
               (((c ^ (uint32_t)((row & 7) << 1)) << 4) | (byte & 15));
    };

    uint32_t rowB[4];
#pragma unroll
    for (int p = 0; p < 4; p++)
        rowB[p] = (uint32_t)(A_BYTES + (wn * 64 + p * 16 + lr) * 128);

    float acc[2][8][4];
#pragma unroll
    for (int mt = 0; mt < 2; mt++)
#pragma unroll
        for (int nt = 0; nt < 8; nt++)
#pragma unroll
            for (int r = 0; r < 4; r++) acc[mt][nt][r] = 0.f;

    // ---- prologue: slab 0 -> slot 0 ----
    load_stage(0, 0);
    CP_COMMIT();

    for (int s = 0; s < NSLAB; s++) {
        CP_WAIT0();
        __syncthreads();

        if (s + 1 < NSLAB)
            load_stage((uint32_t)((s + 1) & 1) * STAGE_BYTES, s + 1);
        CP_COMMIT();

        if (active) {
            const uint32_t stg = (uint32_t)(s & 1) * STAGE_BYTES;
#pragma unroll
            for (int ks = 0; ks < 4; ks++) {
                const uint32_t swk = (uint32_t)(((2 * ks + lh) ^ l7) << 4);
                // Build A hi/lo fragments from fp32 smem.
                uint32_t aH[2][4], aL[2][4];
#pragma unroll
                for (int mt = 0; mt < 2; mt++) {
                    const int ra = wm * 32 + mt * 16 + fr;
                    const int c0 = ks * 16 + fc;
                    float2 v00 = *reinterpret_cast<const float2*>(
                        smem + (a_addr(ra, c0) - sbase) + stg);
                    float2 v10 = *reinterpret_cast<const float2*>(
                        smem + (a_addr(ra + 8, c0) - sbase) + stg);
                    float2 v01 = *reinterpret_cast<const float2*>(
                        smem + (a_addr(ra, c0 + 8) - sbase) + stg);
                    float2 v11 = *reinterpret_cast<const float2*>(
                        smem + (a_addr(ra + 8, c0 + 8) - sbase) + stg);
                    split2(v00, aH[mt][0], aL[mt][0]);
                    split2(v10, aH[mt][1], aL[mt][1]);
                    split2(v01, aH[mt][2], aL[mt][2]);
                    split2(v11, aH[mt][3], aL[mt][3]);
                }
#pragma unroll
                for (int p = 0; p < 4; p++) {
                    uint32_t bH[4];
                    ldsm4(bH, sbase + stg + rowB[p] + swk);
#pragma unroll
                    for (int mt = 0; mt < 2; mt++) {
#pragma unroll
                        for (int t = 0; t < 2; t++) {
                            float* c = acc[mt][2 * p + t];
                            mma16816(c, aH[mt], bH[t], bH[t + 2]);   // hi * bhi
                            mma16816(c, aL[mt], bH[t], bH[t + 2]);   // lo * bhi
                        }
                    }
                }
            }
        }
    }

    // ---- store accumulators to scratch ----
    if (active) {
#pragma unroll
        for (int mt = 0; mt < 2; mt++) {
            const int row = bm + wm * 32 + mt * 16 + fr;
#pragma unroll
            for (int nt = 0; nt < 8; nt++) {
                const int col = bn + wn * 64 + nt * 8 + fc;
                if (col < N_DIM) {
                    float* p0 = &g_scratch[(size_t)row * N_DIM + col];
                    float* p1 = &g_scratch[(size_t)(row + 8) * N_DIM + col];
                    *reinterpret_cast<float2*>(p0) =
                        make_float2(acc[mt][nt][0], acc[mt][nt][1]);
                    *reinterpret_cast<float2*>(p1) =
                        make_float2(acc[mt][nt][2], acc[mt][nt][3]);
                }
            }
        }
    }
}

// ---------------------------------------------------------------------------
// Epilogue: one block per row. Dual RMSNorm + group amax quant + k_pe copy.
// ---------------------------------------------------------------------------
__global__ __launch_bounds__(256)
void epilogue_kernel(const float* __restrict__ wq,
                     const float* __restrict__ wkv,
                     float* __restrict__ out)
{
    const int m   = blockIdx.x;
    const int tid = threadIdx.x;
    const float* row = &g_scratch[(size_t)m * N_DIM];

    __shared__ float s_qn[Q_RANK];
    __shared__ float s_amax[N_GROUPS];
    __shared__ float s_red[16];
    __shared__ float s_rsq[2];

    if (tid < N_GROUPS) s_amax[tid] = 0.f;

    float qs = 0.f, kvs = 0.f;
    for (int i = tid; i < N_DIM / 4; i += 256) {
        float4 v = *reinterpret_cast<const float4*>(row + i * 4);
        int c = i * 4;
        float d = v.x * v.x + v.y * v.y + v.z * v.z + v.w * v.w;
        if (c < Q_RANK)                qs  += d;
        else if (c < Q_RANK + KV_RANK) kvs += d;
        else {
            *reinterpret_cast<float4*>(
                out + OUT_KPE + (size_t)m * ROPE_DIM + (c - Q_RANK - KV_RANK)) = v;
        }
    }
#pragma unroll
    for (int o = 16; o > 0; o >>= 1) {
        qs  += __shfl_down_sync(0xFFFFFFFFu, qs,  o);
        kvs += __shfl_down_sync(0xFFFFFFFFu, kvs, o);
    }
    int wid = tid >> 5, lane = tid & 31;
    if (lane == 0) { s_red[wid] = qs; s_red[8 + wid] = kvs; }
    __syncthreads();
    if (tid == 0) {
        float a = 0.f, b = 0.f;
#pragma unroll
        for (int w = 0; w < 8; w++) { a += s_red[w]; b += s_red[8 + w]; }
        s_rsq[0] = rsqrtf(a / (float)Q_RANK  + EPS_RMS);
        s_rsq[1] = rsqrtf(b / (float)KV_RANK + EPS_RMS);
    }
    __syncthreads();
    const float rq = s_rsq[0], rkv = s_rsq[1];

    for (int i = tid; i < Q_RANK / 4; i += 256) {
        int c = i * 4;
        float4 v = *reinterpret_cast<const float4*>(row + c);
        float4 w = *reinterpret_cast<const float4*>(wq + c);
        float4 q;
        q.x = v.x * rq * w.x;  q.y = v.y * rq * w.y;
        q.z = v.z * rq * w.z;  q.w = v.w * rq * w.w;
        *reinterpret_cast<float4*>(&s_qn[c]) = q;
        float am = fmaxf(fmaxf(fabsf(q.x), fabsf(q.y)),
                         fmaxf(fabsf(q.z), fabsf(q.w)));
        atomicMax(reinterpret_cast<int*>(&s_amax[c >> 7]), __float_as_int(am));
    }
    for (int i = tid; i < KV_RANK / 4; i += 256) {
        int c = i * 4;
        float4 v = *reinterpret_cast<const float4*>(row + Q_RANK + c);
        float4 w = *reinterpret_cast<const float4*>(wkv + c);
        float4 o;
        o.x = v.x * rkv * w.x;  o.y = v.y * rkv * w.y;
        o.z = v.z * rkv * w.z;  o.w = v.w * rkv * w.w;
        *reinterpret_cast<float4*>(out + OUT_KV + (size_t)m * KV_RANK + c) = o;
    }
    __syncthreads();

    if (tid < N_GROUPS) {
        float sc = fmaxf(s_amax[tid] / FP8_MAX, 1e-12f);
        s_amax[tid] = sc;
        out[OUT_SC + (size_t)m * N_GROUPS + tid] = sc;
    }
    __syncthreads();

    for (int i = tid; i < Q_RANK / 4; i += 256) {
        int c = i * 4;
        float inv = 1.0f / s_amax[c >> 7];
        float4 q = *reinterpret_cast<const float4*>(&s_qn[c]);
        float4 o;
        o.x = q.x * inv; o.y = q.y * inv; o.z = q.z * inv; o.w = q.w * inv;
        *reinterpret_cast<float4*>(out + OUT_QQ + (size_t)m * Q_RANK + c) = o;
    }
}

// ---------------------------------------------------------------------------
extern "C" void kernel_launch(void* const* d_in, const int* in_sizes, int n_in,
                              void* d_out, int out_size)
{
    const float* hidden = (const float*)d_in[0];   // [8192, 7168]
    const float* w_qkv  = (const float*)d_in[1];   // [7168, 2112]
    const float* wq     = (const float*)d_in[2];   // [1536]
    const float* wkv    = (const float*)d_in[3];   // [512]
    float* out = (float*)d_out;

    static bool attr_set = false;
    if (!attr_set) {
        cudaFuncSetAttribute(mma_gemm_kernel,
                             cudaFuncAttributeMaxDynamicSharedMemorySize, SMEM_TOTAL);
        attr_set = true;
    }

    convB_kernel<<<dim3(N_PAD / 32, K_DIM / 32), 256>>>(w_qkv);
    mma_gemm_kernel<<<dim3(N_PAD / NT, M_DIM / MT), 256, SMEM_TOTAL>>>(hidden);
    epilogue_kernel<<<M_DIM, 256>>>(wq, wkv, out);
}

// round 14
// speedup vs baseline: 1.6799x; 1.6799x over previous
#include <cuda_runtime.h>
#include <cuda_fp16.h>
#include <cstdint>
#include <cstddef>

// ---------------- problem constants ----------------
#define M_DIM 8192
#define K_DIM 7168
#define N_DIM 2112           // 1536 + 512 + 64
#define Q_RANK 1536
#define KV_RANK 512
#define ROPE_DIM 64
#define N_GROUPS 12
#define FP8_MAX 448.0f
#define EPS_RMS 1e-6f

#define OUT_QQ   ((size_t)0)
#define OUT_SC   ((size_t)M_DIM * Q_RANK)
#define OUT_KV   (OUT_SC + (size_t)M_DIM * N_GROUPS)
#define OUT_KPE  (OUT_KV + (size_t)M_DIM * KV_RANK)

// ---------------- GEMM tiling ----------------
#define MT 128
#define NT 128
#define KB 64                        // fp16 elems per K slab (128 bytes per row)
#define NSLAB (K_DIM / KB)           // 112
#define N_PAD 2176                   // 17 * 128
#define STAGE_BYTES (48 * 1024)      // Ahi 16K | Alo 16K | Bhi 16K
#define NSTAGE 2
#define SMEM_TOTAL (NSTAGE * STAGE_BYTES)   // 96 KB -> 2 CTAs/SM

// fused conv grid split
#define NBLK_A ((M_DIM * (size_t)K_DIM) / (256 * 4))   // 57344
#define NBLK_B_X (N_PAD / 32)                           // 68
#define NBLK_B   (NBLK_B_X * (K_DIM / 32))              // 15232

// ---------------- device scratch (no cudaMalloc allowed) ----------------
__device__ __align__(1024) __half g_Ahi[(size_t)M_DIM * K_DIM];
__device__ __align__(1024) __half g_Alo[(size_t)M_DIM * K_DIM];
__device__ __align__(1024) __half g_Bhi[(size_t)N_PAD * K_DIM];   // [n][k] transposed
__device__ __align__(16)   float  g_scratch[(size_t)M_DIM * N_DIM];

// ---------------- PTX helpers (baseline PTX only: sm_80-era) ----------------
__device__ __forceinline__ uint32_t smem_u32(const void* p) {
    uint32_t a;
    asm("{ .reg .u64 t; cvta.to.shared.u64 t, %1; cvt.u32.u64 %0, t; }" : "=r"(a) : "l"(p));
    return a;
}

__device__ __forceinline__ void cpa16(uint32_t dst, const void* src) {
    asm volatile("cp.async.cg.shared.global [%0], [%1], 16;" :: "r"(dst), "l"(src));
}
#define CP_COMMIT() asm volatile("cp.async.commit_group;" ::: "memory")
#define CP_WAIT0()  asm volatile("cp.async.wait_group 0;"  ::: "memory")

__device__ __forceinline__ void ldsm4(uint32_t* r, uint32_t addr) {
    asm volatile("ldmatrix.sync.aligned.m8n8.x4.shared.b16 {%0,%1,%2,%3}, [%4];"
                 : "=r"(r[0]), "=r"(r[1]), "=r"(r[2]), "=r"(r[3]) : "r"(addr));
}

__device__ __forceinline__ void mma16816(float* c, const uint32_t* a,
                                         uint32_t b0, uint32_t b1) {
    asm volatile(
        "mma.sync.aligned.m16n8k16.row.col.f32.f16.f16.f32 "
        "{%0,%1,%2,%3}, {%4,%5,%6,%7}, {%8,%9}, {%0,%1,%2,%3};"
        : "+f"(c[0]), "+f"(c[1]), "+f"(c[2]), "+f"(c[3])
        : "r"(a[0]), "r"(a[1]), "r"(a[2]), "r"(a[3]), "r"(b0), "r"(b1));
}

// ---------------------------------------------------------------------------
// Fused conversion kernel: blocks [0, NBLK_A) do the fp32 -> fp16 hi/lo split
// of hidden_states; blocks [NBLK_A, NBLK_A+NBLK_B) transpose w_qkv_a into
// fp16 [N_PAD, K]. One launch so both phases share the SM pool.
// ---------------------------------------------------------------------------
__global__ __launch_bounds__(256)
void conv_fused_kernel(const float* __restrict__ A, const float* __restrict__ W)
{
    __shared__ float t[32][33];
    const int tid = threadIdx.x;

    if (blockIdx.x < (unsigned)NBLK_A) {
        // ---- convA: hi/lo double-limb split ----
        size_t i = ((size_t)blockIdx.x * 256 + tid) * 4;
        float4 v = *reinterpret_cast<const float4*>(A + i);
        __half h0 = __float2half(v.x), h1 = __float2half(v.y);
        __half h2 = __float2half(v.z), h3 = __float2half(v.w);
        __half l0 = __float2half(v.x - __half2float(h0));
        __half l1 = __float2half(v.y - __half2float(h1));
        __half l2 = __float2half(v.z - __half2float(h2));
        __half l3 = __float2half(v.w - __half2float(h3));
        __half2 a, b;
        a.x = h0; a.y = h1; b.x = h2; b.y = h3;
        *reinterpret_cast<__half2*>(&g_Ahi[i])     = a;
        *reinterpret_cast<__half2*>(&g_Ahi[i + 2]) = b;
        a.x = l0; a.y = l1; b.x = l2; b.y = l3;
        *reinterpret_cast<__half2*>(&g_Alo[i])     = a;
        *reinterpret_cast<__half2*>(&g_Alo[i + 2]) = b;
    } else {
        // ---- convB: transpose + fp16 convert ----
        const int bid = (int)blockIdx.x - (int)NBLK_A;
        const int nt  = (bid % NBLK_B_X) * 32;
        const int kt  = (bid / NBLK_B_X) * 32;
        const int tx = tid & 31, ty = tid >> 5;

#pragma unroll
        for (int j = 0; j < 4; j++) {
            int k = kt + ty + j * 8;
            int n = nt + tx;
            t[ty + j * 8][tx] = (n < N_DIM) ? W[(size_t)k * N_DIM + n] : 0.f;
        }
        __syncthreads();
#pragma unroll
        for (int j = 0; j < 4; j++) {
            int n = nt + ty + j * 8;
            int k = kt + tx;
            g_Bhi[(size_t)n * K_DIM + k] = __float2half(t[tx][ty + j * 8]);
        }
    }
}

// ---------------------------------------------------------------------------
// GEMM via mma.sync (HMMA): 128x128 block, 256 threads (8 warps, 4m x 2n),
// warp tile 32x64, fp16 2-product ((Ahi+Alo)*Bhi), 2-stage cp.async pipeline,
// single __syncthreads per slab, 2 CTAs per SM. Tail-tile dead work skipped.
//
// Stage layout (384 rows x 128B = 48KB):
//   rows   0-127 : Ahi  (offset 0)
//   rows 128-255 : Alo  (offset 16384)
//   rows 256-383 : Bhi  (offset 32768)
// Within a row, 16B chunk c stored at chunk (c ^ (row & 7)).
// ---------------------------------------------------------------------------
__global__ __launch_bounds__(256, 2)
void mma_gemm_kernel()
{
    extern __shared__ __align__(1024) char smem[];
    const uint32_t sbase = smem_u32(smem);
    const int tid  = threadIdx.x;
    const int bm   = blockIdx.y * MT;
    const int bn   = blockIdx.x * NT;
    const int lane = tid & 31;
    const int wid  = tid >> 5;           // 0..7
    const int wm   = wid & 3;            // m: 4 warps * 32
    const int wn   = wid >> 2;           // n: 2 warps * 64

    const bool active = (bn + wn * 64) < N_DIM;

    // ---- cooperative load: up to 12 x 16B per thread per stage ----
    const int rb    = tid >> 3;          // 0..31
    const int chunk = tid & 7;
    const uint32_t sw = (uint32_t)((chunk ^ (rb & 7)) << 4);
    const uint32_t dbase = sbase + (uint32_t)rb * 128 + sw;

    const char* pAh[4]; const char* pBh[4];
    bool loadB[4];
#pragma unroll
    for (int j = 0; j < 4; j++) {
        pAh[j] = (const char*)(g_Ahi + (size_t)(bm + j * 32 + rb) * K_DIM) + chunk * 16;
        pBh[j] = (const char*)(g_Bhi + (size_t)(bn + j * 32 + rb) * K_DIM) + chunk * 16;
        loadB[j] = (bn + j * 32) < N_DIM;
    }
    const ptrdiff_t dAlo = (const char*)g_Alo - (const char*)g_Ahi;

    auto load_stage = [&](uint32_t soff, size_t koff) {
        uint32_t d = dbase + soff;
#pragma unroll
        for (int j = 0; j < 4; j++) {
            uint32_t dj = d + (uint32_t)j * 4096;
            cpa16(dj,          pAh[j] + koff);          // Ahi
            cpa16(dj + 16384,  pAh[j] + koff + dAlo);   // Alo
            if (loadB[j]) cpa16(dj + 32768, pBh[j] + koff);   // Bhi
        }
    };

    // ---- ldmatrix address constants ----
    const int lr = lane & 15;
    const int lh = lane >> 4;
    const int l7 = lr & 7;
    uint32_t rowA[2], rowB[4];
#pragma unroll
    for (int mt = 0; mt < 2; mt++)
        rowA[mt] = (uint32_t)((wm * 32 + mt * 16 + lr) * 128);
#pragma unroll
    for (int p = 0; p < 4; p++)
        rowB[p] = (uint32_t)(32768 + (wn * 64 + p * 16 + lr) * 128);

    float acc[2][8][4];
#pragma unroll
    for (int mt = 0; mt < 2; mt++)
#pragma unroll
        for (int nt = 0; nt < 8; nt++)
#pragma unroll
            for (int r = 0; r < 4; r++) acc[mt][nt][r] = 0.f;

    // ---- prologue: slab 0 -> slot 0 ----
    load_stage(0, 0);
    CP_COMMIT();

    for (int s = 0; s < NSLAB; s++) {
        CP_WAIT0();
        __syncthreads();

        if (s + 1 < NSLAB)
            load_stage((uint32_t)((s + 1) & 1) * STAGE_BYTES,
                       (size_t)(s + 1) * 128);
        CP_COMMIT();

        if (active) {
            const uint32_t bs = sbase + (uint32_t)(s & 1) * STAGE_BYTES;
#pragma unroll
            for (int ks = 0; ks < 4; ks++) {
                const uint32_t swk = (uint32_t)(((2 * ks + lh) ^ l7) << 4);
                uint32_t aH[2][4], aL[2][4];
#pragma unroll
                for (int mt = 0; mt < 2; mt++) {
                    ldsm4(aH[mt], bs + rowA[mt] + swk);
                    ldsm4(aL[mt], bs + 16384 + rowA[mt] + swk);
                }
#pragma unroll
                for (int p = 0; p < 4; p++) {
                    uint32_t bH[4];
                    ldsm4(bH, bs + rowB[p] + swk);
#pragma unroll
                    for (int mt = 0; mt < 2; mt++) {
#pragma unroll
                        for (int t = 0; t < 2; t++) {
                            float* c = acc[mt][2 * p + t];
                            mma16816(c, aH[mt], bH[t], bH[t + 2]);   // hi * bhi
                            mma16816(c, aL[mt], bH[t], bH[t + 2]);   // lo * bhi
                        }
                    }
                }
            }
        }
    }

    // ---- store accumulators to scratch ----
    if (active) {
#pragma unroll
        for (int mt = 0; mt < 2; mt++) {
            const int row = bm + wm * 32 + mt * 16 + (lane >> 2);
#pragma unroll
            for (int nt = 0; nt < 8; nt++) {
                const int col = bn + wn * 64 + nt * 8 + (lane & 3) * 2;
                if (col < N_DIM) {
                    float* p0 = &g_scratch[(size_t)row * N_DIM + col];
                    float* p1 = &g_scratch[(size_t)(row + 8) * N_DIM + col];
                    *reinterpret_cast<float2*>(p0) =
                        make_float2(acc[mt][nt][0], acc[mt][nt][1]);
                    *reinterpret_cast<float2*>(p1) =
                        make_float2(acc[mt][nt][2], acc[mt][nt][3]);
                }
            }
        }
    }
}

// ---------------------------------------------------------------------------
// Epilogue: ONE WARP PER ROW, fully register-resident. Each lane owns float4
// slots j*32+lane (j=0..16): q = j 0..11, kv = j 12..15, rope = j 16 (lane<16).
// One quant group (128 cols) == 32 float4 == exactly one reg per lane, so
// group amax is a single shfl butterfly. No smem, no __syncthreads.
// ---------------------------------------------------------------------------
__global__ __launch_bounds__(256)
void epilogue_kernel(const float* __restrict__ wq,
                     const float* __restrict__ wkv,
                     float* __restrict__ out)
{
    const int warp = threadIdx.x >> 5;
    const int lane = threadIdx.x & 31;
    const int m    = blockIdx.x * 8 + warp;
    const float* row = g_scratch + (size_t)m * N_DIM;

    float4 q[12], kv[4], rope;
#pragma unroll
    for (int j = 0; j < 12; j++)
        q[j] = *reinterpret_cast<const float4*>(row + (j * 32 + lane) * 4);
#pragma unroll
    for (int j = 0; j < 4; j++)
        kv[j] = *reinterpret_cast<const float4*>(row + ((12 + j) * 32 + lane) * 4);
    if (lane < 16)
        rope = *reinterpret_cast<const float4*>(row + (512 + lane) * 4);

    // ---- RMS sums (shfl butterfly so every lane gets the result) ----
    float qs = 0.f, kvs = 0.f;
#pragma unroll
    for (int j = 0; j < 12; j++)
        qs += q[j].x * q[j].x + q[j].y * q[j].y + q[j].z * q[j].z + q[j].w * q[j].w;
#pragma unroll
    for (int j = 0; j < 4; j++)
        kvs += kv[j].x * kv[j].x + kv[j].y * kv[j].y + kv[j].z * kv[j].z + kv[j].w * kv[j].w;
#pragma unroll
    for (int o = 16; o > 0; o >>= 1) {
        qs  += __shfl_xor_sync(0xFFFFFFFFu, qs,  o);
        kvs += __shfl_xor_sync(0xFFFFFFFFu, kvs, o);
    }
    const float rq  = rsqrtf(qs  / (float)Q_RANK  + EPS_RMS);
    const float rkv = rsqrtf(kvs / (float)KV_RANK + EPS_RMS);

    // ---- rope passthrough ----
    if (lane < 16)
        *reinterpret_cast<float4*>(out + OUT_KPE + (size_t)m * ROPE_DIM + lane * 4) = rope;

    // ---- kv normalize ----
#pragma unroll
    for (int j = 0; j < 4; j++) {
        float4 w = *reinterpret_cast<const float4*>(wkv + (j * 32 + lane) * 4);
        float4 o;
        o.x = kv[j].x * rkv * w.x;  o.y = kv[j].y * rkv * w.y;
        o.z = kv[j].z * rkv * w.z;  o.w = kv[j].w * rkv * w.w;
        *reinterpret_cast<float4*>(
            out + OUT_KV + (size_t)m * KV_RANK + (j * 32 + lane) * 4) = o;
    }

    // ---- q normalize, per-group amax (one butterfly per group), quant ----
    float sc_mine = 0.f;
#pragma unroll
    for (int j = 0; j < 12; j++) {
        float4 w = *reinterpret_cast<const float4*>(wq + (j * 32 + lane) * 4);
        float4 qn;
        qn.x = q[j].x * rq * w.x;  qn.y = q[j].y * rq * w.y;
        qn.z = q[j].z * rq * w.z;  qn.w = q[j].w * rq * w.w;
        float am = fmaxf(fmaxf(fabsf(qn.x), fabsf(qn.y)),
                         fmaxf(fabsf(qn.z), fabsf(qn.w)));
#pragma unroll
        for (int o = 16; o > 0; o >>= 1)
            am = fmaxf(am, __shfl_xor_sync(0xFFFFFFFFu, am, o));
        float sc = fmaxf(am / FP8_MAX, 1e-12f);
        if (lane == j) sc_mine = sc;
        float inv = 1.0f / sc;
        float4 o;
        o.x = qn.x * inv; o.y = qn.y * inv; o.z = qn.z * inv; o.w = qn.w * inv;
        *reinterpret_cast<float4*>(
            out + OUT_QQ + (size_t)m * Q_RANK + (j * 32 + lane) * 4) = o;
    }
    if (lane < N_GROUPS)
        out[OUT_SC + (size_t)m * N_GROUPS + lane] = sc_mine;
}

// ---------------------------------------------------------------------------
extern "C" void kernel_launch(void* const* d_in, const int* in_sizes, int n_in,
                              void* d_out, int out_size)
{
    const float* hidden = (const float*)d_in[0];   // [8192, 7168]
    const float* w_qkv  = (const float*)d_in[1];   // [7168, 2112]
    const float* wq     = (const float*)d_in[2];   // [1536]
    const float* wkv    = (const float*)d_in[3];   // [512]
    float* out = (float*)d_out;

    static bool attr_set = false;
    if (!attr_set) {
        cudaFuncSetAttribute(mma_gemm_kernel,
                             cudaFuncAttributeMaxDynamicSharedMemorySize, SMEM_TOTAL);
        attr_set = true;
    }

    conv_fused_kernel<<<(unsigned)(NBLK_A + NBLK_B), 256>>>(hidden, w_qkv);
    mma_gemm_kernel<<<dim3(N_PAD / NT, M_DIM / MT), 256, SMEM_TOTAL>>>();
    epilogue_kernel<<<M_DIM / 8, 256>>>(wq, wkv, out);
}

// round 15
// speedup vs baseline: 1.6871x; 1.0043x over previous
#include <cuda_runtime.h>
#include <cuda_fp16.h>
#include <cstdint>
#include <cstddef>

// ---------------- problem constants ----------------
#define M_DIM 8192
#define K_DIM 7168
#define N_DIM 2112           // 1536 + 512 + 64
#define Q_RANK 1536
#define KV_RANK 512
#define ROPE_DIM 64
#define N_GROUPS 12
#define FP8_MAX 448.0f
#define EPS_RMS 1e-6f

#define OUT_QQ   ((size_t)0)
#define OUT_SC   ((size_t)M_DIM * Q_RANK)
#define OUT_KV   (OUT_SC + (size_t)M_DIM * N_GROUPS)
#define OUT_KPE  (OUT_KV + (size_t)M_DIM * KV_RANK)

// ---------------- GEMM tiling ----------------
#define MT 128
#define NT 128
#define KB 64                        // fp16 elems per K slab (128 bytes per row)
#define NSLAB (K_DIM / KB)           // 112
#define N_PAD 2176                   // 17 * 128
#define STAGE_BYTES (48 * 1024)      // Ahi 16K | Alo 16K | Bhi 16K
#define NSTAGE 2
#define SMEM_TOTAL (NSTAGE * STAGE_BYTES)   // 96 KB -> 2 CTAs/SM

// conv grid split
#define NBLK_A      ((int)((M_DIM * (size_t)K_DIM) / (256 * 4)))  // 57344
#define NBLK_A_HALF (NBLK_A / 2)                                   // 28672
#define NBLK_B_X    (N_PAD / 32)                                   // 68
#define NBLK_B      (NBLK_B_X * (K_DIM / 32))                      // 15232

// ---------------- device scratch (no cudaMalloc allowed) ----------------
__device__ __align__(1024) __half g_Ahi[(size_t)M_DIM * K_DIM];
__device__ __align__(1024) __half g_Alo[(size_t)M_DIM * K_DIM];
__device__ __align__(1024) __half g_Bhi[(size_t)N_PAD * K_DIM];   // [n][k] transposed
__device__ __align__(16)   float  g_scratch[(size_t)M_DIM * N_DIM];

// ---------------- PTX helpers (baseline PTX only: sm_80-era) ----------------
__device__ __forceinline__ uint32_t smem_u32(const void* p) {
    uint32_t a;
    asm("{ .reg .u64 t; cvta.to.shared.u64 t, %1; cvt.u32.u64 %0, t; }" : "=r"(a) : "l"(p));
    return a;
}

__device__ __forceinline__ void cpa16(uint32_t dst, const void* src) {
    asm volatile("cp.async.cg.shared.global [%0], [%1], 16;" :: "r"(dst), "l"(src));
}
#define CP_COMMIT() asm volatile("cp.async.commit_group;" ::: "memory")
#define CP_WAIT0()  asm volatile("cp.async.wait_group 0;"  ::: "memory")

__device__ __forceinline__ void ldsm4(uint32_t* r, uint32_t addr) {
    asm volatile("ldmatrix.sync.aligned.m8n8.x4.shared.b16 {%0,%1,%2,%3}, [%4];"
                 : "=r"(r[0]), "=r"(r[1]), "=r"(r[2]), "=r"(r[3]) : "r"(addr));
}

__device__ __forceinline__ void mma16816(float* c, const uint32_t* a,
                                         uint32_t b0, uint32_t b1) {
    asm volatile(
        "mma.sync.aligned.m16n8k16.row.col.f32.f16.f16.f32 "
        "{%0,%1,%2,%3}, {%4,%5,%6,%7}, {%8,%9}, {%0,%1,%2,%3};"
        : "+f"(c[0]), "+f"(c[1]), "+f"(c[2]), "+f"(c[3])
        : "r"(a[0]), "r"(a[1]), "r"(a[2]), "r"(a[3]), "r"(b0), "r"(b1));
}

// ---------------------------------------------------------------------------
// Conversion kernel (split-capable): blocks [0, aCount) do the fp32 -> fp16
// hi/lo split of hidden_states chunks [aStart, aStart+aCount); blocks beyond
// aCount transpose w_qkv_a (only present in the part-1 launch).
// ---------------------------------------------------------------------------
__global__ __launch_bounds__(256)
void conv_kernel(const float* __restrict__ A, const float* __restrict__ W,
                 int aStart, int aCount)
{
    __shared__ float t[32][33];
    const int tid = threadIdx.x;

    if ((int)blockIdx.x < aCount) {
        // ---- convA: hi/lo double-limb split ----
        size_t i = (((size_t)aStart + blockIdx.x) * 256 + tid) * 4;
        float4 v = *reinterpret_cast<const float4*>(A + i);
        __half h0 = __float2half(v.x), h1 = __float2half(v.y);
        __half h2 = __float2half(v.z), h3 = __float2half(v.w);
        __half l0 = __float2half(v.x - __half2float(h0));
        __half l1 = __float2half(v.y - __half2float(h1));
        __half l2 = __float2half(v.z - __half2float(h2));
        __half l3 = __float2half(v.w - __half2float(h3));
        __half2 a, b;
        a.x = h0; a.y = h1; b.x = h2; b.y = h3;
        *reinterpret_cast<__half2*>(&g_Ahi[i])     = a;
        *reinterpret_cast<__half2*>(&g_Ahi[i + 2]) = b;
        a.x = l0; a.y = l1; b.x = l2; b.y = l3;
        *reinterpret_cast<__half2*>(&g_Alo[i])     = a;
        *reinterpret_cast<__half2*>(&g_Alo[i + 2]) = b;
    } else {
        // ---- convB: transpose + fp16 convert ----
        const int bid = (int)blockIdx.x - aCount;
        const int nt  = (bid % NBLK_B_X) * 32;
        const int kt  = (bid / NBLK_B_X) * 32;
        const int tx = tid & 31, ty = tid >> 5;

#pragma unroll
        for (int j = 0; j < 4; j++) {
            int k = kt + ty + j * 8;
            int n = nt + tx;
            t[ty + j * 8][tx] = (n < N_DIM) ? W[(size_t)k * N_DIM + n] : 0.f;
        }
        __syncthreads();
#pragma unroll
        for (int j = 0; j < 4; j++) {
            int n = nt + ty + j * 8;
            int k = kt + tx;
            g_Bhi[(size_t)n * K_DIM + k] = __float2half(t[tx][ty + j * 8]);
        }
    }
}

// ---------------------------------------------------------------------------
// GEMM via mma.sync (HMMA): 128x128 block, 256 threads (8 warps, 4m x 2n),
// warp tile 32x64, fp16 2-product ((Ahi+Alo)*Bhi), 2-stage cp.async pipeline,
// single __syncthreads per slab, 2 CTAs per SM. Tail-tile dead work skipped.
// mOff: M-tile offset (kernel is launched in two M-halves on forked streams).
// ---------------------------------------------------------------------------
__global__ __launch_bounds__(256, 2)
void mma_gemm_kernel(int mOff)
{
    extern __shared__ __align__(1024) char smem[];
    const uint32_t sbase = smem_u32(smem);
    const int tid  = threadIdx.x;
    const int bm   = (blockIdx.y + mOff) * MT;
    const int bn   = blockIdx.x * NT;
    const int lane = tid & 31;
    const int wid  = tid >> 5;           // 0..7
    const int wm   = wid & 3;            // m: 4 warps * 32
    const int wn   = wid >> 2;           // n: 2 warps * 64

    const bool active = (bn + wn * 64) < N_DIM;

    // ---- cooperative load: up to 12 x 16B per thread per stage ----
    const int rb    = tid >> 3;          // 0..31
    const int chunk = tid & 7;
    const uint32_t sw = (uint32_t)((chunk ^ (rb & 7)) << 4);
    const uint32_t dbase = sbase + (uint32_t)rb * 128 + sw;

    const char* pAh[4]; const char* pBh[4];
    bool loadB[4];
#pragma unroll
    for (int j = 0; j < 4; j++) {
        pAh[j] = (const char*)(g_Ahi + (size_t)(bm + j * 32 + rb) * K_DIM) + chunk * 16;
        pBh[j] = (const char*)(g_Bhi + (size_t)(bn + j * 32 + rb) * K_DIM) + chunk * 16;
        loadB[j] = (bn + j * 32) < N_DIM;
    }
    const ptrdiff_t dAlo = (const char*)g_Alo - (const char*)g_Ahi;

    auto load_stage = [&](uint32_t soff, size_t koff) {
        uint32_t d = dbase + soff;
#pragma unroll
        for (int j = 0; j < 4; j++) {
            uint32_t dj = d + (uint32_t)j * 4096;
            cpa16(dj,          pAh[j] + koff);          // Ahi
            cpa16(dj + 16384,  pAh[j] + koff + dAlo);   // Alo
            if (loadB[j]) cpa16(dj + 32768, pBh[j] + koff);   // Bhi
        }
    };

    // ---- ldmatrix address constants ----
    const int lr = lane & 15;
    const int lh = lane >> 4;
    const int l7 = lr & 7;
    uint32_t rowA[2], rowB[4];
#pragma unroll
    for (int mt = 0; mt < 2; mt++)
        rowA[mt] = (uint32_t)((wm * 32 + mt * 16 + lr) * 128);
#pragma unroll
    for (int p = 0; p < 4; p++)
        rowB[p] = (uint32_t)(32768 + (wn * 64 + p * 16 + lr) * 128);

    float acc[2][8][4];
#pragma unroll
    for (int mt = 0; mt < 2; mt++)
#pragma unroll
        for (int nt = 0; nt < 8; nt++)
#pragma unroll
            for (int r = 0; r < 4; r++) acc[mt][nt][r] = 0.f;

    // ---- prologue: slab 0 -> slot 0 ----
    load_stage(0, 0);
    CP_COMMIT();

    for (int s = 0; s < NSLAB; s++) {
        CP_WAIT0();
        __syncthreads();

        if (s + 1 < NSLAB)
            load_stage((uint32_t)((s + 1) & 1) * STAGE_BYTES,
                       (size_t)(s + 1) * 128);
        CP_COMMIT();

        if (active) {
            const uint32_t bs = sbase + (uint32_t)(s & 1) * STAGE_BYTES;
#pragma unroll
            for (int ks = 0; ks < 4; ks++) {
                const uint32_t swk = (uint32_t)(((2 * ks + lh) ^ l7) << 4);
                uint32_t aH[2][4], aL[2][4];
#pragma unroll
                for (int mt = 0; mt < 2; mt++) {
                    ldsm4(aH[mt], bs + rowA[mt] + swk);
                    ldsm4(aL[mt], bs + 16384 + rowA[mt] + swk);
                }
#pragma unroll
                for (int p = 0; p < 4; p++) {
                    uint32_t bH[4];
                    ldsm4(bH, bs + rowB[p] + swk);
#pragma unroll
                    for (int mt = 0; mt < 2; mt++) {
#pragma unroll
                        for (int t = 0; t < 2; t++) {
                            float* c = acc[mt][2 * p + t];
                            mma16816(c, aH[mt], bH[t], bH[t + 2]);   // hi * bhi
                            mma16816(c, aL[mt], bH[t], bH[t + 2]);   // lo * bhi
                        }
                    }
                }
            }
        }
    }

    // ---- store accumulators to scratch ----
    if (active) {
#pragma unroll
        for (int mt = 0; mt < 2; mt++) {
            const int row = bm + wm * 32 + mt * 16 + (lane >> 2);
#pragma unroll
            for (int nt = 0; nt < 8; nt++) {
                const int col = bn + wn * 64 + nt * 8 + (lane & 3) * 2;
                if (col < N_DIM) {
                    float* p0 = &g_scratch[(size_t)row * N_DIM + col];
                    float* p1 = &g_scratch[(size_t)(row + 8) * N_DIM + col];
                    *reinterpret_cast<float2*>(p0) =
                        make_float2(acc[mt][nt][0], acc[mt][nt][1]);
                    *reinterpret_cast<float2*>(p1) =
                        make_float2(acc[mt][nt][2], acc[mt][nt][3]);
                }
            }
        }
    }
}

// ---------------------------------------------------------------------------
// Epilogue: ONE WARP PER ROW, fully register-resident (see R14). mOff: row
// offset for the M-half split.
// ---------------------------------------------------------------------------
__global__ __launch_bounds__(256)
void epilogue_kernel(const float* __restrict__ wq,
                     const float* __restrict__ wkv,
                     float* __restrict__ out, int mOff)
{
    const int warp = threadIdx.x >> 5;
    const int lane = threadIdx.x & 31;
    const int m    = mOff + blockIdx.x * 8 + warp;
    const float* row = g_scratch + (size_t)m * N_DIM;

    float4 q[12], kv[4], rope;
#pragma unroll
    for (int j = 0; j < 12; j++)
        q[j] = *reinterpret_cast<const float4*>(row + (j * 32 + lane) * 4);
#pragma unroll
    for (int j = 0; j < 4; j++)
        kv[j] = *reinterpret_cast<const float4*>(row + ((12 + j) * 32 + lane) * 4);
    if (lane < 16)
        rope = *reinterpret_cast<const float4*>(row + (512 + lane) * 4);

    float qs = 0.f, kvs = 0.f;
#pragma unroll
    for (int j = 0; j < 12; j++)
        qs += q[j].x * q[j].x + q[j].y * q[j].y + q[j].z * q[j].z + q[j].w * q[j].w;
#pragma unroll
    for (int j = 0; j < 4; j++)
        kvs += kv[j].x * kv[j].x + kv[j].y * kv[j].y + kv[j].z * kv[j].z + kv[j].w * kv[j].w;
#pragma unroll
    for (int o = 16; o > 0; o >>= 1) {
        qs  += __shfl_xor_sync(0xFFFFFFFFu, qs,  o);
        kvs += __shfl_xor_sync(0xFFFFFFFFu, kvs, o);
    }
    const float rq  = rsqrtf(qs  / (float)Q_RANK  + EPS_RMS);
    const float rkv = rsqrtf(kvs / (float)KV_RANK + EPS_RMS);

    if (lane < 16)
        *reinterpret_cast<float4*>(out + OUT_KPE + (size_t)m * ROPE_DIM + lane * 4) = rope;

#pragma unroll
    for (int j = 0; j < 4; j++) {
        float4 w = *reinterpret_cast<const float4*>(wkv + (j * 32 + lane) * 4);
        float4 o;
        o.x = kv[j].x * rkv * w.x;  o.y = kv[j].y * rkv * w.y;
        o.z = kv[j].z * rkv * w.z;  o.w = kv[j].w * rkv * w.w;
        *reinterpret_cast<float4*>(
            out + OUT_KV + (size_t)m * KV_RANK + (j * 32 + lane) * 4) = o;
    }

    float sc_mine = 0.f;
#pragma unroll
    for (int j = 0; j < 12; j++) {
        float4 w = *reinterpret_cast<const float4*>(wq + (j * 32 + lane) * 4);
        float4 qn;
        qn.x = q[j].x * rq * w.x;  qn.y = q[j].y * rq * w.y;
        qn.z = q[j].z * rq * w.z;  qn.w = q[j].w * rq * w.w;
        float am = fmaxf(fmaxf(fabsf(qn.x), fabsf(qn.y)),
                         fmaxf(fabsf(qn.z), fabsf(qn.w)));
#pragma unroll
        for (int o = 16; o > 0; o >>= 1)
            am = fmaxf(am, __shfl_xor_sync(0xFFFFFFFFu, am, o));
        float sc = fmaxf(am / FP8_MAX, 1e-12f);
        if (lane == j) sc_mine = sc;
        float inv = 1.0f / sc;
        float4 o;
        o.x = qn.x * inv; o.y = qn.y * inv; o.z = qn.z * inv; o.w = qn.w * inv;
        *reinterpret_cast<float4*>(
            out + OUT_QQ + (size_t)m * Q_RANK + (j * 32 + lane) * 4) = o;
    }
    if (lane < N_GROUPS)
        out[OUT_SC + (size_t)m * N_GROUPS + lane] = sc_mine;
}

// ---------------------------------------------------------------------------
// Launch: fork-join stream overlap (capture-legal).
//   stream0: conv1(A half1 + B) -ev1-> conv2(A half2) -ev2-> ... epi1, epi2
//   s2: wait ev1 -> GEMM1 (bm 0..31)  -> evG1
//   s3: wait ev2 -> GEMM2 (bm 32..63) -> evG2
// conv2 overlaps GEMM1; epi1 overlaps GEMM2; GEMM1/GEMM2 on separate streams
// so drain tails backfill each other. Streams/events created once in the
// uncaptured correctness call; event edges become graph dependencies.
// ---------------------------------------------------------------------------
extern "C" void kernel_launch(void* const* d_in, const int* in_sizes, int n_in,
                              void* d_out, int out_size)
{
    const float* hidden = (const float*)d_in[0];   // [8192, 7168]
    const float* w_qkv  = (const float*)d_in[1];   // [7168, 2112]
    const float* wq     = (const float*)d_in[2];   // [1536]
    const float* wkv    = (const float*)d_in[3];   // [512]
    float* out = (float*)d_out;

    static bool init = false;
    static cudaStream_t s2, s3;
    static cudaEvent_t ev1, ev2, evG1, evG2;
    if (!init) {
        cudaFuncSetAttribute(mma_gemm_kernel,
                             cudaFuncAttributeMaxDynamicSharedMemorySize, SMEM_TOTAL);
        cudaStreamCreateWithFlags(&s2, cudaStreamNonBlocking);
        cudaStreamCreateWithFlags(&s3, cudaStreamNonBlocking);
        cudaEventCreateWithFlags(&ev1,  cudaEventDisableTiming);
        cudaEventCreateWithFlags(&ev2,  cudaEventDisableTiming);
        cudaEventCreateWithFlags(&evG1, cudaEventDisableTiming);
        cudaEventCreateWithFlags(&evG2, cudaEventDisableTiming);
        init = true;
    }

    // conv part 1: A rows 0..4095 + all of B
    conv_kernel<<<NBLK_A_HALF + NBLK_B, 256>>>(hidden, w_qkv, 0, NBLK_A_HALF);
    cudaEventRecord(ev1, 0);
    // conv part 2: A rows 4096..8191
    conv_kernel<<<NBLK_A_HALF, 256>>>(hidden, w_qkv, NBLK_A_HALF, NBLK_A_HALF);
    cudaEventRecord(ev2, 0);

    // GEMM halves on forked streams
    cudaStreamWaitEvent(s2, ev1, 0);
    mma_gemm_kernel<<<dim3(N_PAD / NT, 32), 256, SMEM_TOTAL, s2>>>(0);
    cudaEventRecord(evG1, s2);

    cudaStreamWaitEvent(s3, ev2, 0);
    mma_gemm_kernel<<<dim3(N_PAD / NT, 32), 256, SMEM_TOTAL, s3>>>(32);
    cudaEventRecord(evG2, s3);

    // Epilogues join back on stream 0
    cudaStreamWaitEvent(0, evG1, 0);
    epilogue_kernel<<<(M_DIM / 2) / 8, 256>>>(wq, wkv, out, 0);
    cudaStreamWaitEvent(0, evG2, 0);
    epilogue_kernel<<<(M_DIM / 2) / 8, 256>>>(wq, wkv, out, M_DIM / 2);
}

// round 17
// speedup vs baseline: 1.6949x; 1.0046x over previous
#include <cuda_runtime.h>
#include <cuda_fp16.h>
#include <cstdint>
#include <cstddef>

// ---------------- problem constants ----------------
#define M_DIM 8192
#define K_DIM 7168
#define N_DIM 2112           // 1536 + 512 + 64
#define Q_RANK 1536
#define KV_RANK 512
#define ROPE_DIM 64
#define N_GROUPS 12
#define FP8_MAX 448.0f
#define EPS_RMS 1e-6f

#define OUT_QQ   ((size_t)0)
#define OUT_SC   ((size_t)M_DIM * Q_RANK)
#define OUT_KV   (OUT_SC + (size_t)M_DIM * N_GROUPS)
#define OUT_KPE  (OUT_KV + (size_t)M_DIM * KV_RANK)

// ---------------- GEMM tiling (3 CTAs/SM variant) ----------------
#define MT 64
#define NT 128
#define KB 64                        // fp16 elems per K slab (128 bytes per row)
#define NSLAB (K_DIM / KB)           // 112
#define N_PAD 2176                   // 17 * 128
// Stage: Ahi 8K | Alo 8K | Bhi 16K = 32KB; 2 stages = 64KB -> 3 CTAs/SM
#define ALO_OFF 8192
#define B_OFF   16384
#define STAGE_BYTES (32 * 1024)
#define SMEM_TOTAL (2 * STAGE_BYTES)

// conv grid split (2-way, R15-proven launch structure)
#define NBLK_A      ((int)((M_DIM * (size_t)K_DIM) / (256 * 4)))  // 57344
#define NBLK_A_HALF (NBLK_A / 2)                                   // 28672
#define NBLK_B_X    (N_PAD / 32)                                   // 68
#define NBLK_B      (NBLK_B_X * (K_DIM / 32))                      // 15232

// ---------------- device scratch (no cudaMalloc allowed) ----------------
__device__ __align__(1024) __half g_Ahi[(size_t)M_DIM * K_DIM];
__device__ __align__(1024) __half g_Alo[(size_t)M_DIM * K_DIM];
__device__ __align__(1024) __half g_Bhi[(size_t)N_PAD * K_DIM];   // [n][k] transposed
__device__ __align__(16)   float  g_scratch[(size_t)M_DIM * N_DIM];

// ---------------- PTX helpers (baseline PTX only: sm_80-era) ----------------
__device__ __forceinline__ uint32_t smem_u32(const void* p) {
    uint32_t a;
    asm("{ .reg .u64 t; cvta.to.shared.u64 t, %1; cvt.u32.u64 %0, t; }" : "=r"(a) : "l"(p));
    return a;
}

__device__ __forceinline__ void cpa16(uint32_t dst, const void* src) {
    asm volatile("cp.async.cg.shared.global [%0], [%1], 16;" :: "r"(dst), "l"(src));
}
#define CP_COMMIT() asm volatile("cp.async.commit_group;" ::: "memory")
#define CP_WAIT0()  asm volatile("cp.async.wait_group 0;"  ::: "memory")

__device__ __forceinline__ void ldsm4(uint32_t* r, uint32_t addr) {
    asm volatile("ldmatrix.sync.aligned.m8n8.x4.shared.b16 {%0,%1,%2,%3}, [%4];"
                 : "=r"(r[0]), "=r"(r[1]), "=r"(r[2]), "=r"(r[3]) : "r"(addr));
}

__device__ __forceinline__ void mma16816(float* c, const uint32_t* a,
                                         uint32_t b0, uint32_t b1) {
    asm volatile(
        "mma.sync.aligned.m16n8k16.row.col.f32.f16.f16.f32 "
        "{%0,%1,%2,%3}, {%4,%5,%6,%7}, {%8,%9}, {%0,%1,%2,%3};"
        : "+f"(c[0]), "+f"(c[1]), "+f"(c[2]), "+f"(c[3])
        : "r"(a[0]), "r"(a[1]), "r"(a[2]), "r"(a[3]), "r"(b0), "r"(b1));
}

// ---------------------------------------------------------------------------
// Conversion kernel (split-capable): blocks [0, aCount) split hidden_states
// chunks [aStart, aStart+aCount); blocks beyond transpose w_qkv_a.
// ---------------------------------------------------------------------------
__global__ __launch_bounds__(256)
void conv_kernel(const float* __restrict__ A, const float* __restrict__ W,
                 int aStart, int aCount)
{
    __shared__ float t[32][33];
    const int tid = threadIdx.x;

    if ((int)blockIdx.x < aCount) {
        size_t i = (((size_t)aStart + blockIdx.x) * 256 + tid) * 4;
        float4 v = *reinterpret_cast<const float4*>(A + i);
        __half h0 = __float2half(v.x), h1 = __float2half(v.y);
        __half h2 = __float2half(v.z), h3 = __float2half(v.w);
        __half l0 = __float2half(v.x - __half2float(h0));
        __half l1 = __float2half(v.y - __half2float(h1));
        __half l2 = __float2half(v.z - __half2float(h2));
        __half l3 = __float2half(v.w - __half2float(h3));
        __half2 a, b;
        a.x = h0; a.y = h1; b.x = h2; b.y = h3;
        *reinterpret_cast<__half2*>(&g_Ahi[i])     = a;
        *reinterpret_cast<__half2*>(&g_Ahi[i + 2]) = b;
        a.x = l0; a.y = l1; b.x = l2; b.y = l3;
        *reinterpret_cast<__half2*>(&g_Alo[i])     = a;
        *reinterpret_cast<__half2*>(&g_Alo[i + 2]) = b;
    } else {
        const int bid = (int)blockIdx.x - aCount;
        const int nt  = (bid % NBLK_B_X) * 32;
        const int kt  = (bid / NBLK_B_X) * 32;
        const int tx = tid & 31, ty = tid >> 5;

#pragma unroll
        for (int j = 0; j < 4; j++) {
            int k = kt + ty + j * 8;
            int n = nt + tx;
            t[ty + j * 8][tx] = (n < N_DIM) ? W[(size_t)k * N_DIM + n] : 0.f;
        }
        __syncthreads();
#pragma unroll
        for (int j = 0; j < 4; j++) {
            int n = nt + ty + j * 8;
            int k = kt + tx;
            g_Bhi[(size_t)n * K_DIM + k] = __float2half(t[tx][ty + j * 8]);
        }
    }
}

// ---------------------------------------------------------------------------
// GEMM via mma.sync (HMMA): 64x128 block, 256 threads (8 warps, 2m x 4n),
// warp tile 32x32, fp16 2-product ((Ahi+Alo)*Bhi), 2-stage cp.async pipeline,
// single __syncthreads per slab, 3 CTAs/SM (64KB smem, <=85 regs) -> 24
// warps/SM = 6/SMSP for latency hiding (R15 profile: tensor 60%, occ-capped).
//
// Stage layout (32KB): Ahi rows 0-63 (off 0) | Alo rows 0-63 (off 8192) |
//                      Bhi rows 0-127 (off 16384); 128B rows, chunk^(row&7).
// ---------------------------------------------------------------------------
__global__ __launch_bounds__(256, 3)
void mma_gemm_kernel(int mOff)
{
    extern __shared__ __align__(1024) char smem[];
    const uint32_t sbase = smem_u32(smem);
    const int tid  = threadIdx.x;
    const int bm   = (blockIdx.y + mOff) * MT;
    const int bn   = blockIdx.x * NT;
    const int lane = tid & 31;
    const int wid  = tid >> 5;           // 0..7
    const int wm   = wid & 1;            // m: 2 warps * 32
    const int wn   = wid >> 1;           // n: 4 warps * 32

    const bool active = (bn + wn * 32) < N_DIM;   // tail-tile guard

    // ---- cooperative load: 8 x 16B per thread per stage ----
    const int rb    = tid >> 3;          // 0..31
    const int chunk = tid & 7;
    const uint32_t sw = (uint32_t)((chunk ^ (rb & 7)) << 4);
    const uint32_t dbase = sbase + (uint32_t)rb * 128 + sw;

    const char* pAh[2]; const char* pBh[4];
    bool loadB[4];
#pragma unroll
    for (int j = 0; j < 2; j++)
        pAh[j] = (const char*)(g_Ahi + (size_t)(bm + j * 32 + rb) * K_DIM) + chunk * 16;
#pragma unroll
    for (int j = 0; j < 4; j++) {
        pBh[j] = (const char*)(g_Bhi + (size_t)(bn + j * 32 + rb) * K_DIM) + chunk * 16;
        loadB[j] = (bn + j * 32) < N_DIM;
    }
    const ptrdiff_t dAlo = (const char*)g_Alo - (const char*)g_Ahi;

    auto load_stage = [&](uint32_t soff, size_t koff) {
        uint32_t d = dbase + soff;
#pragma unroll
        for (int j = 0; j < 2; j++) {
            cpa16(d + (uint32_t)j * 4096,           pAh[j] + koff);          // Ahi
            cpa16(d + ALO_OFF + (uint32_t)j * 4096, pAh[j] + koff + dAlo);   // Alo
        }
#pragma unroll
        for (int j = 0; j < 4; j++) {
            if (loadB[j])
                cpa16(d + B_OFF + (uint32_t)j * 4096, pBh[j] + koff);        // Bhi
        }
    };

    // ---- ldmatrix address constants ----
    const int lr = lane & 15;
    const int lh = lane >> 4;
    const int l7 = lr & 7;
    uint32_t rowA[2], rowB[2];
#pragma unroll
    for (int mt = 0; mt < 2; mt++)
        rowA[mt] = (uint32_t)((wm * 32 + mt * 16 + lr) * 128);
#pragma unroll
    for (int p = 0; p < 2; p++)
        rowB[p] = (uint32_t)(B_OFF + (wn * 32 + p * 16 + lr) * 128);

    float acc[2][4][4];
#pragma unroll
    for (int mt = 0; mt < 2; mt++)
#pragma unroll
        for (int nt = 0; nt < 4; nt++)
#pragma unroll
            for (int r = 0; r < 4; r++) acc[mt][nt][r] = 0.f;

    // ---- prologue: slab 0 -> slot 0 ----
    load_stage(0, 0);
    CP_COMMIT();

    for (int s = 0; s < NSLAB; s++) {
        CP_WAIT0();              // all committed groups done -> slab s resident
        __syncthreads();         // data visible; slot (s+1)&1 free

        if (s + 1 < NSLAB)
            load_stage((uint32_t)((s + 1) & 1) * STAGE_BYTES,
                       (size_t)(s + 1) * 128);
        CP_COMMIT();

        if (active) {
            const uint32_t bs = sbase + (uint32_t)(s & 1) * STAGE_BYTES;
#pragma unroll
            for (int ks = 0; ks < 4; ks++) {
                const uint32_t swk = (uint32_t)(((2 * ks + lh) ^ l7) << 4);
                uint32_t aH[2][4], aL[2][4];
#pragma unroll
                for (int mt = 0; mt < 2; mt++) {
                    ldsm4(aH[mt], bs + rowA[mt] + swk);
                    ldsm4(aL[mt], bs + ALO_OFF + rowA[mt] + swk);
                }
#pragma unroll
                for (int p = 0; p < 2; p++) {
                    uint32_t bH[4];
                    ldsm4(bH, bs + rowB[p] + swk);
#pragma unroll
                    for (int mt = 0; mt < 2; mt++) {
#pragma unroll
                        for (int t = 0; t < 2; t++) {
                            float* c = acc[mt][2 * p + t];
                            mma16816(c, aH[mt], bH[t], bH[t + 2]);   // hi * bhi
                            mma16816(c, aL[mt], bH[t], bH[t + 2]);   // lo * bhi
                        }
                    }
                }
            }
        }
    }

    // ---- store accumulators to scratch ----
    if (active) {
#pragma unroll
        for (int mt = 0; mt < 2; mt++) {
            const int row = bm + wm * 32 + mt * 16 + (lane >> 2);
#pragma unroll
            for (int nt = 0; nt < 4; nt++) {
                const int col = bn + wn * 32 + nt * 8 + (lane & 3) * 2;
                if (col < N_DIM) {
                    float* p0 = &g_scratch[(size_t)row * N_DIM + col];
                    float* p1 = &g_scratch[(size_t)(row + 8) * N_DIM + col];
                    *reinterpret_cast<float2*>(p0) =
                        make_float2(acc[mt][nt][0], acc[mt][nt][1]);
                    *reinterpret_cast<float2*>(p1) =
                        make_float2(acc[mt][nt][2], acc[mt][nt][3]);
                }
            }
        }
    }
}

// ---------------------------------------------------------------------------
// Epilogue: one warp per row, register-resident (see R14). mOff = row offset.
// ---------------------------------------------------------------------------
__global__ __launch_bounds__(256)
void epilogue_kernel(const float* __restrict__ wq,
                     const float* __restrict__ wkv,
                     float* __restrict__ out, int mOff)
{
    const int warp = threadIdx.x >> 5;
    const int lane = threadIdx.x & 31;
    const int m    = mOff + blockIdx.x * 8 + warp;
    const float* row = g_scratch + (size_t)m * N_DIM;

    float4 q[12], kv[4], rope;
#pragma unroll
    for (int j = 0; j < 12; j++)
        q[j] = *reinterpret_cast<const float4*>(row + (j * 32 + lane) * 4);
#pragma unroll
    for (int j = 0; j < 4; j++)
        kv[j] = *reinterpret_cast<const float4*>(row + ((12 + j) * 32 + lane) * 4);
    if (lane < 16)
        rope = *reinterpret_cast<const float4*>(row + (512 + lane) * 4);

    float qs = 0.f, kvs = 0.f;
#pragma unroll
    for (int j = 0; j < 12; j++)
        qs += q[j].x * q[j].x + q[j].y * q[j].y + q[j].z * q[j].z + q[j].w * q[j].w;
#pragma unroll
    for (int j = 0; j < 4; j++)
        kvs += kv[j].x * kv[j].x + kv[j].y * kv[j].y + kv[j].z * kv[j].z + kv[j].w * kv[j].w;
#pragma unroll
    for (int o = 16; o > 0; o >>= 1) {
        qs  += __shfl_xor_sync(0xFFFFFFFFu, qs,  o);
        kvs += __shfl_xor_sync(0xFFFFFFFFu, kvs, o);
    }
    const float rq  = rsqrtf(qs  / (float)Q_RANK  + EPS_RMS);
    const float rkv = rsqrtf(kvs / (float)KV_RANK + EPS_RMS);

    if (lane < 16)
        *reinterpret_cast<float4*>(out + OUT_KPE + (size_t)m * ROPE_DIM + lane * 4) = rope;

#pragma unroll
    for (int j = 0; j < 4; j++) {
        float4 w = *reinterpret_cast<const float4*>(wkv + (j * 32 + lane) * 4);
        float4 o;
        o.x = kv[j].x * rkv * w.x;  o.y = kv[j].y * rkv * w.y;
        o.z = kv[j].z * rkv * w.z;  o.w = kv[j].w * rkv * w.w;
        *reinterpret_cast<float4*>(
            out + OUT_KV + (size_t)m * KV_RANK + (j * 32 + lane) * 4) = o;
    }

    float sc_mine = 0.f;
#pragma unroll
    for (int j = 0; j < 12; j++) {
        float4 w = *reinterpret_cast<const float4*>(wq + (j * 32 + lane) * 4);
        float4 qn;
        qn.x = q[j].x * rq * w.x;  qn.y = q[j].y * rq * w.y;
        qn.z = q[j].z * rq * w.z;  qn.w = q[j].w * rq * w.w;
        float am = fmaxf(fmaxf(fabsf(qn.x), fabsf(qn.y)),
                         fmaxf(fabsf(qn.z), fabsf(qn.w)));
#pragma unroll
        for (int o = 16; o > 0; o >>= 1)
            am = fmaxf(am, __shfl_xor_sync(0xFFFFFFFFu, am, o));
        float sc = fmaxf(am / FP8_MAX, 1e-12f);
        if (lane == j) sc_mine = sc;
        float inv = 1.0f / sc;
        float4 o;
        o.x = qn.x * inv; o.y = qn.y * inv; o.z = qn.z * inv; o.w = qn.w * inv;
        *reinterpret_cast<float4*>(
            out + OUT_QQ + (size_t)m * Q_RANK + (j * 32 + lane) * 4) = o;
    }
    if (lane < N_GROUPS)
        out[OUT_SC + (size_t)m * N_GROUPS + lane] = sc_mine;
}

// ---------------------------------------------------------------------------
// Launch: R15-proven fork-join (2 streams + 4 events; stays inside the
// driver's already-allocated resource pool -> no teardown-guard trip).
// ---------------------------------------------------------------------------
extern "C" void kernel_launch(void* const* d_in, const int* in_sizes, int n_in,
                              void* d_out, int out_size)
{
    const float* hidden = (const float*)d_in[0];   // [8192, 7168]
    const float* w_qkv  = (const float*)d_in[1];   // [7168, 2112]
    const float* wq     = (const float*)d_in[2];   // [1536]
    const float* wkv    = (const float*)d_in[3];   // [512]
    float* out = (float*)d_out;

    static bool init = false;
    static cudaStream_t s2, s3;
    static cudaEvent_t ev1, ev2, evG1, evG2;
    if (!init) {
        cudaFuncSetAttribute(mma_gemm_kernel,
                             cudaFuncAttributeMaxDynamicSharedMemorySize, SMEM_TOTAL);
        cudaStreamCreateWithFlags(&s2, cudaStreamNonBlocking);
        cudaStreamCreateWithFlags(&s3, cudaStreamNonBlocking);
        cudaEventCreateWithFlags(&ev1,  cudaEventDisableTiming);
        cudaEventCreateWithFlags(&ev2,  cudaEventDisableTiming);
        cudaEventCreateWithFlags(&evG1, cudaEventDisableTiming);
        cudaEventCreateWithFlags(&evG2, cudaEventDisableTiming);
        init = true;
    }

    // conv part 1: A rows 0..4095 + all of B
    conv_kernel<<<NBLK_A_HALF + NBLK_B, 256>>>(hidden, w_qkv, 0, NBLK_A_HALF);
    cudaEventRecord(ev1, 0);
    // conv part 2: A rows 4096..8191
    conv_kernel<<<NBLK_A_HALF, 256>>>(hidden, w_qkv, NBLK_A_HALF, NBLK_A_HALF);
    cudaEventRecord(ev2, 0);

    // GEMM halves (64 M-tiles of 64 rows each) on forked streams
    cudaStreamWaitEvent(s2, ev1, 0);
    mma_gemm_kernel<<<dim3(N_PAD / NT, 64), 256, SMEM_TOTAL, s2>>>(0);
    cudaEventRecord(evG1, s2);

    cudaStreamWaitEvent(s3, ev2, 0);
    mma_gemm_kernel<<<dim3(N_PAD / NT, 64), 256, SMEM_TOTAL, s3>>>(64);
    cudaEventRecord(evG2, s3);

    // Epilogues join back on stream 0
    cudaStreamWaitEvent(0, evG1, 0);
    epilogue_kernel<<<(M_DIM / 2) / 8, 256>>>(wq, wkv, out, 0);
    cudaStreamWaitEvent(0, evG2, 0);
    epilogue_kernel<<<(M_DIM / 2) / 8, 256>>>(wq, wkv, out, M_DIM / 2);
}